// round 7
// baseline (speedup 1.0000x reference)
#include <cuda_runtime.h>

#define NSEG 16384
#define DFEAT 128
#define EPSV 1e-10f
#define TILE 32                // rows per tile
#define ROWPAD 132             // floats per smem row (528 B) -> bank-rotating
#define NTHR 128               // threads per block
#define NB 888                 // ~6 blocks/SM * 148 SMs

// Scratch (allocation-free requirement -> __device__ globals)
__device__ float g_pooled[NSEG * DFEAT];   // 8 MB
__device__ float g_denom[NSEG];

__device__ __forceinline__ void cpasync16(void* dst, const void* src) {
    unsigned d = (unsigned)__cvta_generic_to_shared(dst);
    asm volatile("cp.async.cg.shared.global [%0], [%1], 16;\n" :: "r"(d), "l"(src));
}
__device__ __forceinline__ void cpcommit() {
    asm volatile("cp.async.commit_group;\n");
}
template <int N> __device__ __forceinline__ void cpwait() {
    asm volatile("cp.async.wait_group %0;\n" :: "n"(N));
}

// ---------------------------------------------------------------------------
// Kernel 0: zero the scratch accumulators (grid-stride float4)
// ---------------------------------------------------------------------------
__global__ void zero_scratch_kernel() {
    const int stride = gridDim.x * blockDim.x;
    const float4 z = make_float4(0.f, 0.f, 0.f, 0.f);
    float4* p4 = reinterpret_cast<float4*>(g_pooled);
    for (int i = blockIdx.x * blockDim.x + threadIdx.x;
         i < NSEG * DFEAT / 4; i += stride)
        p4[i] = z;
    float4* d4 = reinterpret_cast<float4*>(g_denom);
    for (int i = blockIdx.x * blockDim.x + threadIdx.x;
         i < NSEG / 4; i += stride)
        d4[i] = z;
}

// ---------------------------------------------------------------------------
// Kernel 1: fused gate + weighted segment pooling, 2-stage cp.async pipeline
// with STATIC shared memory (~34 KB) so ~6 blocks/SM provide the in-flight
// load depth (6 x 17 KB per SM) instead of registers or huge dynamic smem.
// Per tile (32 rows x 128 f32):
//   Phase A: 4 threads/row -> gate logit from smem (2 shfls), e -> e_s
//   Phase B: warp-per-8-rows accumulates e*x; sorted-index register
//            accumulation, atomic flush at segment boundaries.
// wait discipline: wait_group<1> while the newer commit group is real,
// wait_group<0> on the last iteration (empty groups complete instantly and
// must not be counted as cover).
// ---------------------------------------------------------------------------
__global__ void __launch_bounds__(NTHR) gate_pool_kernel(
    const float* __restrict__ x,          // [N,128]
    const int*   __restrict__ index,      // [N] sorted
    const float* __restrict__ weights,    // [N]
    const float* __restrict__ gate_w,     // [128]
    const float* __restrict__ gate_b,     // [1]
    const float* __restrict__ pow_p,      // [1]
    int n_rows, int tiles_total, int tpb)
{
    __shared__ float tile_s[2][TILE * ROWPAD];   // 33792 B
    __shared__ float w_s[2][TILE];
    __shared__ int   si_s[2][TILE];
    __shared__ float gw_s[DFEAT];
    __shared__ float e_s[TILE];

    const int tid  = threadIdx.x;
    const int lane = tid & 31;
    const int wid  = tid >> 5;

    const int tb0 = blockIdx.x * tpb;
    const int tb1 = min(tiles_total, tb0 + tpb);
    if (tb0 >= tiles_total) return;

    if (tid < DFEAT) gw_s[tid] = gate_w[tid];
    const float gb = __ldg(gate_b);
    const float p  = __ldg(pow_p);

    auto issue = [&](int t) {
        const int stage = t & 1;
        const int r0    = t * TILE;
        const int rows  = min(TILE, n_rows - r0);
        const float* sb = x + (size_t)r0 * DFEAT;
        for (int c = tid; c < rows * 32; c += NTHR)
            cpasync16(&tile_s[stage][(c >> 5) * ROWPAD + (c & 31) * 4],
                      sb + (size_t)(c >> 5) * DFEAT + (c & 31) * 4);
        if (tid < 8 && tid * 4 < rows) {
            cpasync16(&w_s[stage][tid * 4],  weights + r0 + tid * 4);
            cpasync16(&si_s[stage][tid * 4], index   + r0 + tid * 4);
        }
        cpcommit();
    };

    issue(tb0);

    float4 acc = make_float4(0.f, 0.f, 0.f, 0.f);
    float dsum = 0.f;
    int cur = -1;            // sentinel: nothing accumulated yet

    for (int t = tb0; t < tb1; ++t) {
        const int stage = t & 1;
        const int rows  = min(TILE, n_rows - t * TILE);

        if (t + 1 < tb1) { issue(t + 1); cpwait<1>(); }
        else             { cpwait<0>(); }
        __syncthreads();                 // tile t visible to all threads

        // ---- Phase A: gate logits (4 threads per row)
        {
            const int row = tid >> 2;    // 0..31
            const int q   = tid & 3;
            const float* rp = &tile_s[stage][row * ROWPAD];
            float a0 = 0.f, a1 = 0.f;
            #pragma unroll
            for (int i = 0; i < 8; ++i) {
                const int k4 = q + 4 * i;
                const float4 v = *(const float4*)(rp + k4 * 4);
                const float4 g = *(const float4*)(gw_s + k4 * 4);
                const float d = v.x * g.x + v.y * g.y + v.z * g.z + v.w * g.w;
                if (i & 1) a1 += d; else a0 += d;
            }
            float part = a0 + a1;
            part += __shfl_xor_sync(0xffffffffu, part, 1);
            part += __shfl_xor_sync(0xffffffffu, part, 2);
            if (q == 0 && row < rows) {
                const float w = w_s[stage][row];
                e_s[row] = __expf(__fmaf_rn(p, __logf(w), part + gb));
            }
        }
        __syncthreads();

        // ---- Phase B: gated accumulation (warp-per-8-rows)
        {
            const float* tb = tile_s[stage];
            const int rbase = wid * 8;
            #pragma unroll
            for (int rr = 0; rr < 8; ++rr) {
                const int row = rbase + rr;
                if (row >= rows) break;
                const int   seg = si_s[stage][row];
                const float ev  = e_s[row];
                const float4 xv = *(const float4*)(tb + row * ROWPAD + lane * 4);
                if (seg != cur) {
                    if (cur >= 0) {
                        float* dst = &g_pooled[cur * DFEAT + lane * 4];
                        atomicAdd(dst + 0, acc.x);
                        atomicAdd(dst + 1, acc.y);
                        atomicAdd(dst + 2, acc.z);
                        atomicAdd(dst + 3, acc.w);
                        if (lane == 0) atomicAdd(&g_denom[cur], dsum);
                    }
                    acc = make_float4(0.f, 0.f, 0.f, 0.f);
                    dsum = 0.f;
                    cur = seg;
                }
                acc.x += ev * xv.x;
                acc.y += ev * xv.y;
                acc.z += ev * xv.z;
                acc.w += ev * xv.w;
                dsum  += ev;
            }
        }
        __syncthreads();                 // Phase B done before stage reuse
    }

    if (cur >= 0) {
        float* dst = &g_pooled[cur * DFEAT + lane * 4];
        atomicAdd(dst + 0, acc.x);
        atomicAdd(dst + 1, acc.y);
        atomicAdd(dst + 2, acc.z);
        atomicAdd(dst + 3, acc.w);
        if (lane == 0) atomicAdd(&g_denom[cur], dsum);
    }
}

// ---------------------------------------------------------------------------
// Kernel 2: out[s] = (pooled[s]/(denom[s]+eps)) @ msg_w
//                    + (denom[s]/(denom[s]+eps)) * msg_b
// ---------------------------------------------------------------------------
__global__ void __launch_bounds__(256) out_gemm_kernel(
    const float* __restrict__ msg_w,      // [128,128] row-major (k, n)
    const float* __restrict__ msg_b,      // [128]
    float*       __restrict__ out)        // [NSEG,128]
{
    __shared__ float pr[16][DFEAT];
    __shared__ float gsh[16];

    const int s0 = blockIdx.x * 16;
    const int tid = threadIdx.x;

    #pragma unroll
    for (int i = tid; i < 16 * DFEAT; i += 256) {
        const int rr = i >> 7;
        const float den = g_denom[s0 + rr];
        pr[rr][i & 127] = g_pooled[(s0 + rr) * DFEAT + (i & 127)] / (den + EPSV);
    }
    if (tid < 16) {
        const float den = g_denom[s0 + tid];
        gsh[tid] = den / (den + EPSV);
    }
    __syncthreads();

    const int c  = tid & 31;
    const int rg = tid >> 5;
    const int r0 = rg * 2;
    const int r1 = rg * 2 + 1;

    const float4* mw4 = reinterpret_cast<const float4*>(msg_w);
    const float4  mb  = reinterpret_cast<const float4*>(msg_b)[c];

    float4 a0 = make_float4(0.f, 0.f, 0.f, 0.f);
    float4 a1 = make_float4(0.f, 0.f, 0.f, 0.f);

    #pragma unroll 4
    for (int k = 0; k < DFEAT; ++k) {
        const float4 m = mw4[k * 32 + c];
        const float p0 = pr[r0][k];
        const float p1 = pr[r1][k];
        a0.x += p0 * m.x; a0.y += p0 * m.y; a0.z += p0 * m.z; a0.w += p0 * m.w;
        a1.x += p1 * m.x; a1.y += p1 * m.y; a1.z += p1 * m.z; a1.w += p1 * m.w;
    }

    const float g0 = gsh[r0];
    const float g1 = gsh[r1];
    float4 o0 = make_float4(a0.x + g0 * mb.x, a0.y + g0 * mb.y,
                            a0.z + g0 * mb.z, a0.w + g0 * mb.w);
    float4 o1 = make_float4(a1.x + g1 * mb.x, a1.y + g1 * mb.y,
                            a1.z + g1 * mb.z, a1.w + g1 * mb.w);

    reinterpret_cast<float4*>(out)[(size_t)(s0 + r0) * 32 + c] = o0;
    reinterpret_cast<float4*>(out)[(size_t)(s0 + r1) * 32 + c] = o1;
}

// ---------------------------------------------------------------------------
// Launch. Inputs: x, index, weights, gate_w, gate_b, msg_w, msg_b, pow_p.
// Output: [16384,128] f32.
// ---------------------------------------------------------------------------
extern "C" void kernel_launch(void* const* d_in, const int* in_sizes, int n_in,
                              void* d_out, int out_size)
{
    const float* x       = (const float*)d_in[0];
    const int*   index   = (const int*)  d_in[1];
    const float* weights = (const float*)d_in[2];
    const float* gate_w  = (const float*)d_in[3];
    const float* gate_b  = (const float*)d_in[4];
    const float* msg_w   = (const float*)d_in[5];
    const float* msg_b   = (const float*)d_in[6];
    const float* pow_p   = (const float*)d_in[7];
    float* out = (float*)d_out;

    const int n_rows = in_sizes[1];

    // 0) zero scratch
    zero_scratch_kernel<<<2048, 256>>>();

    // 1) fused gate + pooling (static-smem cp.async pipeline)
    {
        const int tiles_total = (n_rows + TILE - 1) / TILE;
        const int nb  = min(NB, tiles_total);
        const int tpb = (tiles_total + nb - 1) / nb;
        gate_pool_kernel<<<nb, NTHR>>>(
            x, index, weights, gate_w, gate_b, pow_p,
            n_rows, tiles_total, tpb);
    }

    // 2) small GEMM epilogue
    out_gemm_kernel<<<NSEG / 16, 256>>>(msg_w, msg_b, out);
}